// round 15
// baseline (speedup 1.0000x reference)
#include <cuda_runtime.h>
#include <cuda_bf16.h>
#include <math.h>

#define BB 8
#define NN 256
#define DD 48
#define VV 20
#define LL 2
#define SS 6
#define TWO_D 96
#define THREE_D 144
#define FOUR_D 192
#define ROWS (BB*NN)   // 2048

// Scratch
__device__ float g_x[ROWS * DD];
__device__ float g_p[ROWS * DD];
__device__ float g_t[ROWS * DD];
__device__ float g_A[ROWS * TWO_D];   // xi @ W1_top + b1
__device__ float g_B[ROWS * TWO_D];   // xj @ W1_bot

// Fast erf-based gelu (A&S 7.1.26, max abs err 1.5e-7), copysign-free:
// v*erf(v/sqrt2) = |v|*erf(|v|/sqrt2)  =>  gelu = relu(v) - 0.5|v|*poly*e^{-z^2}
__device__ __forceinline__ float gelu_exact(float v) {
    float az = fabsf(v) * 0.70710678118654752440f;
    float w = fmaf(0.3275911f, az, 1.0f);
    float t;
    asm("rcp.approx.f32 %0, %1;" : "=f"(t) : "f"(w));
    float poly = fmaf(1.061405429f, t, -1.453152027f);
    poly = fmaf(poly, t, 1.421413741f);
    poly = fmaf(poly, t, -0.284496736f);
    poly = fmaf(poly, t, 0.254829592f);
    poly = poly * t;
    float e = __expf(-az * az);
    float s = 0.5f * fabsf(v);
    return fmaf(-s * poly, e, fmaxf(v, 0.0f));
}

__device__ __forceinline__ unsigned smem_u32(const void* p) {
    return (unsigned)__cvta_generic_to_shared(p);
}

__device__ __forceinline__ void ldsm4(unsigned r[4], unsigned addr) {
    asm volatile("ldmatrix.sync.aligned.m8n8.x4.shared.b16 {%0,%1,%2,%3}, [%4];"
                 : "=r"(r[0]), "=r"(r[1]), "=r"(r[2]), "=r"(r[3]) : "r"(addr));
}

__device__ __forceinline__ void mma16816(float c[4], const unsigned a[4],
                                         unsigned b0, unsigned b1) {
    asm volatile("mma.sync.aligned.m16n8k16.row.col.f32.bf16.bf16.f32 "
                 "{%0,%1,%2,%3}, {%4,%5,%6,%7}, {%8,%9}, {%0,%1,%2,%3};"
                 : "+f"(c[0]), "+f"(c[1]), "+f"(c[2]), "+f"(c[3])
                 : "r"(a[0]), "r"(a[1]), "r"(a[2]), "r"(a[3]), "r"(b0), "r"(b1));
}

// ---------------------------------------------------------------------------
// Embed
// ---------------------------------------------------------------------------
__global__ void embed_kernel(const int* __restrict__ ids,
                             const float* __restrict__ embed,
                             const float* __restrict__ pos,
                             float* __restrict__ x) {
    int row = blockIdx.x;
    int n = row & (NN - 1);
    int d = threadIdx.x;
    int id = ids[row];
    x[row * DD + d] = embed[id * DD + d] + pos[n * DD + d];
}

// ---------------------------------------------------------------------------
// Precompute A[row][96] = b1 + xi @ W1[0:48,:],  B[row][96] = xj @ W1[48:96,:]
// ---------------------------------------------------------------------------
__global__ __launch_bounds__(192) void ab_kernel(const float* __restrict__ x,
                          const float* __restrict__ W1,
                          const float* __restrict__ b1,
                          float* __restrict__ A,
                          float* __restrict__ Bv) {
    __shared__ float sx[8][DD];
    int r0 = blockIdx.x * 8;
    int tid = threadIdx.x;
    for (int idx = tid; idx < 8 * DD; idx += 192)
        sx[idx / DD][idx % DD] = x[(r0 + idx / DD) * DD + (idx % DD)];
    __syncthreads();
    int col = tid % TWO_D;
    int part = tid / TWO_D;   // 0 = A, 1 = B
    const float* w = W1 + (part ? DD * TWO_D : 0) + col;
    float acc[8];
    float init = part ? 0.0f : b1[col];
    #pragma unroll
    for (int r = 0; r < 8; r++) acc[r] = init;
    #pragma unroll 4
    for (int k = 0; k < DD; k++) {
        float wv = w[k * TWO_D];
        #pragma unroll
        for (int r = 0; r < 8; r++) acc[r] = fmaf(sx[r][k], wv, acc[r]);
    }
    float* dst = part ? Bv : A;
    #pragma unroll
    for (int r = 0; r < 8; r++) dst[(r0 + r) * TWO_D + col] = acc[r];
}

// ---------------------------------------------------------------------------
// Pair module on tensor cores, k-split H tiles, div-free H-build (R13).
// ---------------------------------------------------------------------------
#define PJT 64
#define PTHREADS 128
#define HPITU 28   // H row pitch in u32 (= 112 B)
#define WPIT 104   // W row pitch in bf16 (= 208 B)

__global__ __launch_bounds__(PTHREADS, 5) void pair_kernel(
    const float* __restrict__ A, const float* __restrict__ Bv,
    const float* __restrict__ W2, const float* __restrict__ B2,
    float* __restrict__ outp) {
    __shared__ __align__(16) unsigned Hhi[PJT * HPITU];
    __shared__ __align__(16) unsigned Hlo[PJT * HPITU];
    __shared__ __align__(16) __nv_bfloat16 Whi[DD * WPIT];
    __shared__ __align__(16) __nv_bfloat16 Wlo[DD * WPIT];
    __shared__ __align__(16) float sA[TWO_D];
    __shared__ float sb2[DD];
    __shared__ float sacc[4 * DD];
    __shared__ float slsum[4];

    int row = blockIdx.x;
    int b = row >> 8;
    int i = row & (NN - 1);
    int tid = threadIdx.x;
    int lane = tid & 31;
    int w = tid >> 5;

    // W^T hi/lo build: incremental (k, n4) walk, no per-iter div/mod.
    {
        int k = tid / 12;
        int n4g = tid - k * 12;
        #pragma unroll
        for (int it = 0; it < 9; it++) {
            int n4 = n4g * 4;
            float4 wv = *(const float4*)(W2 + k * DD + n4);
            float vals[4] = {wv.x, wv.y, wv.z, wv.w};
            #pragma unroll
            for (int q = 0; q < 4; q++) {
                int n = n4 + q;
                __nv_bfloat16 hb = __float2bfloat16(vals[q]);
                Whi[n * WPIT + k] = hb;
                Wlo[n * WPIT + k] = __float2bfloat16(vals[q] - __bfloat162float(hb));
            }
            k += 10; n4g += 8;
            if (n4g >= 12) { n4g -= 12; k += 1; }
        }
    }
    if (tid < TWO_D) sA[tid] = A[row * TWO_D + tid];
    if (tid < DD) sb2[tid] = B2[tid];
    __syncthreads();

    float bcol[6][2];
    #pragma unroll
    for (int n = 0; n < 6; n++) {
        bcol[n][0] = sb2[n * 8 + 2 * (lane & 3)];
        bcol[n][1] = sb2[n * 8 + 2 * (lane & 3) + 1];
    }
    unsigned aoff = (unsigned)((w * 16 + (lane & 15)) * 112 + (lane >> 4) * 16);
    unsigned baseAhi = smem_u32(Hhi) + aoff;
    unsigned baseAlo = smem_u32(Hlo) + aoff;
    unsigned boff = (unsigned)((((lane >> 4) << 3) + (lane & 7)) * 208 +
                               ((lane >> 3) & 1) * 16);
    unsigned baseBhi = smem_u32(Whi) + boff;
    unsigned baseBlo = smem_u32(Wlo) + boff;

    int jh = tid >> 1;
    int hs6 = (tid & 1) * 6;
    unsigned* Hhirow = Hhi + jh * HPITU;
    unsigned* Hlorow = Hlo + jh * HPITU;

    float accD[6][2];
    #pragma unroll
    for (int n = 0; n < 6; n++) { accD[n][0] = 0.0f; accD[n][1] = 0.0f; }
    float lsum = 0.0f;

    int numJ = i + 1;
    const float* Bbase = Bv + (b * NN) * TWO_D;

    for (int jbase = 0; jbase < numJ; jbase += PJT) {
        float c[6][4];
        #pragma unroll
        for (int n = 0; n < 6; n++)
            #pragma unroll
            for (int q = 0; q < 4; q++) c[n][q] = 0.0f;

        int jr = jbase + jh; if (jr > i) jr = i;
        const float* brow = Bbase + jr * TWO_D;

        #pragma unroll
        for (int kh = 0; kh < 2; kh++) {
            #pragma unroll
            for (int it = 0; it < 6; it++) {
                int c4 = hs6 + it;
                int kk = kh * 48 + c4 * 4;
                float4 bv = *(const float4*)(brow + kk);
                float4 av = *(const float4*)(sA + kk);
                float h0 = gelu_exact(av.x + bv.x);
                float h1 = gelu_exact(av.y + bv.y);
                float h2 = gelu_exact(av.z + bv.z);
                float h3 = gelu_exact(av.w + bv.w);
                __nv_bfloat162 p01 = __floats2bfloat162_rn(h0, h1);
                __nv_bfloat162 p23 = __floats2bfloat162_rn(h2, h3);
                float r0 = __low2float(p01), r1 = __high2float(p01);
                float r2 = __low2float(p23), r3 = __high2float(p23);
                __nv_bfloat162 q01 = __floats2bfloat162_rn(h0 - r0, h1 - r1);
                __nv_bfloat162 q23 = __floats2bfloat162_rn(h2 - r2, h3 - r3);
                *(uint2*)(Hhirow + c4 * 2) =
                    make_uint2(*(unsigned*)&p01, *(unsigned*)&p23);
                *(uint2*)(Hlorow + c4 * 2) =
                    make_uint2(*(unsigned*)&q01, *(unsigned*)&q23);
            }
            __syncthreads();

            unsigned ahi[4], alo[4], bh[4], bl[4];
            #pragma unroll
            for (int ks = 0; ks < 3; ks++) {
                ldsm4(ahi, baseAhi + ks * 32);
                ldsm4(alo, baseAlo + ks * 32);
                unsigned wko = (unsigned)(kh * 96 + ks * 32);
                #pragma unroll
                for (int np = 0; np < 3; np++) {
                    ldsm4(bh, baseBhi + np * 3328 + wko);
                    ldsm4(bl, baseBlo + np * 3328 + wko);
                    mma16816(c[2 * np + 0], ahi, bh[0], bh[1]);
                    mma16816(c[2 * np + 0], ahi, bl[0], bl[1]);
                    mma16816(c[2 * np + 0], alo, bh[0], bh[1]);
                    mma16816(c[2 * np + 1], ahi, bh[2], bh[3]);
                    mma16816(c[2 * np + 1], ahi, bl[2], bl[3]);
                    mma16816(c[2 * np + 1], alo, bh[2], bh[3]);
                }
            }
            __syncthreads();
        }

        float pv[6][4];
        float sq0 = 0.0f, sq1 = 0.0f;
        #pragma unroll
        for (int n = 0; n < 6; n++) {
            pv[n][0] = c[n][0] + bcol[n][0];
            pv[n][1] = c[n][1] + bcol[n][1];
            pv[n][2] = c[n][2] + bcol[n][0];
            pv[n][3] = c[n][3] + bcol[n][1];
            sq0 = fmaf(pv[n][0], pv[n][0], sq0);
            sq0 = fmaf(pv[n][1], pv[n][1], sq0);
            sq1 = fmaf(pv[n][2], pv[n][2], sq1);
            sq1 = fmaf(pv[n][3], pv[n][3], sq1);
        }
        sq0 += __shfl_xor_sync(0xFFFFFFFFu, sq0, 1);
        sq0 += __shfl_xor_sync(0xFFFFFFFFu, sq0, 2);
        sq1 += __shfl_xor_sync(0xFFFFFFFFu, sq1, 1);
        sq1 += __shfl_xor_sync(0xFFFFFFFFu, sq1, 2);
        int j0 = jbase + w * 16 + (lane >> 2);
        int j1 = j0 + 8;
        float e0 = (j0 <= i) ? __expf(sqrtf(sq0)) : 0.0f;
        float e1 = (j1 <= i) ? __expf(sqrtf(sq1)) : 0.0f;
        #pragma unroll
        for (int n = 0; n < 6; n++) {
            accD[n][0] = fmaf(e0, pv[n][0], fmaf(e1, pv[n][2], accD[n][0]));
            accD[n][1] = fmaf(e0, pv[n][1], fmaf(e1, pv[n][3], accD[n][1]));
        }
        lsum += e0 + e1;
    }

    #pragma unroll
    for (int n = 0; n < 6; n++) {
        #pragma unroll
        for (int q = 0; q < 2; q++) {
            accD[n][q] += __shfl_xor_sync(0xFFFFFFFFu, accD[n][q], 4);
            accD[n][q] += __shfl_xor_sync(0xFFFFFFFFu, accD[n][q], 8);
            accD[n][q] += __shfl_xor_sync(0xFFFFFFFFu, accD[n][q], 16);
        }
    }
    lsum += __shfl_xor_sync(0xFFFFFFFFu, lsum, 4);
    lsum += __shfl_xor_sync(0xFFFFFFFFu, lsum, 8);
    lsum += __shfl_xor_sync(0xFFFFFFFFu, lsum, 16);
    if (lane < 4) {
        #pragma unroll
        for (int n = 0; n < 6; n++) {
            sacc[w * DD + n * 8 + 2 * lane + 0] = accD[n][0];
            sacc[w * DD + n * 8 + 2 * lane + 1] = accD[n][1];
        }
        if (lane == 0) slsum[w] = lsum;
    }
    __syncthreads();

    if (tid < DD) {
        float a = sacc[tid] + sacc[DD + tid] + sacc[2 * DD + tid] + sacc[3 * DD + tid];
        float L = slsum[0] + slsum[1] + slsum[2] + slsum[3];
        outp[row * DD + tid] = a / L;
    }
}

// ---------------------------------------------------------------------------
// Triple module: one row per block, 6-item batch, coalesced W (R13).
// ---------------------------------------------------------------------------
__global__ __launch_bounds__(TWO_D) void triple_kernel(const float* __restrict__ x,
                              const int* __restrict__ ji,
                              const int* __restrict__ ki,
                              const float* __restrict__ W1,
                              const float* __restrict__ B1,
                              const float* __restrict__ W2,
                              const float* __restrict__ B2,
                              float* __restrict__ outt) {
    __shared__ __align__(16) float v[SS][THREE_D];
    __shared__ __align__(16) float hh[SS][TWO_D];
    __shared__ float sp2[2][DD];
    __shared__ int sidx[SS][2];
    int row = blockIdx.x;
    int b = row >> 8;
    int tid = threadIdx.x;     // 96

    if (tid < SS * 2) {
        int s = tid >> 1;
        sidx[s][tid & 1] = (tid & 1) ? ki[row * SS + s] : ji[row * SS + s];
    }
    __syncthreads();

    for (int q = tid; q < SS * 36; q += TWO_D) {
        int s = q / 36;
        int rem = q % 36;
        int seg = rem / 12;
        int f4 = rem % 12;
        int srcrow = (seg == 0) ? row : (b * NN + sidx[s][seg - 1]);
        float4 val = *(const float4*)(x + srcrow * DD + f4 * 4);
        *(float4*)(&v[s][seg * DD + f4 * 4]) = val;
    }
    __syncthreads();

    {
        float h[SS];
        float bb = B1[tid];
        #pragma unroll
        for (int s = 0; s < SS; s++) h[s] = bb;
        const float* w1c = W1 + tid;
        #pragma unroll 3
        for (int k = 0; k < THREE_D; k += 4) {
            float w0 = w1c[(k + 0) * TWO_D];
            float w1 = w1c[(k + 1) * TWO_D];
            float w2 = w1c[(k + 2) * TWO_D];
            float w3 = w1c[(k + 3) * TWO_D];
            #pragma unroll
            for (int s = 0; s < SS; s++) {
                float4 vv = *(const float4*)(&v[s][k]);
                h[s] = fmaf(vv.x, w0, h[s]);
                h[s] = fmaf(vv.y, w1, h[s]);
                h[s] = fmaf(vv.z, w2, h[s]);
                h[s] = fmaf(vv.w, w3, h[s]);
            }
        }
        #pragma unroll
        for (int s = 0; s < SS; s++) hh[s][tid] = gelu_exact(h[s]);
    }
    __syncthreads();

    {
        int col = tid % DD;
        int g = tid / DD;
        float p[3];
        float bb = B2[col];
        #pragma unroll
        for (int q = 0; q < 3; q++) p[q] = bb;
        const float* w2c = W2 + col;
        #pragma unroll 3
        for (int k = 0; k < TWO_D; k += 4) {
            float w0 = w2c[(k + 0) * DD];
            float w1 = w2c[(k + 1) * DD];
            float w2 = w2c[(k + 2) * DD];
            float w3 = w2c[(k + 3) * DD];
            #pragma unroll
            for (int q = 0; q < 3; q++) {
                float4 hv = *(const float4*)(&hh[g * 3 + q][k]);
                p[q] = fmaf(hv.x, w0, p[q]);
                p[q] = fmaf(hv.y, w1, p[q]);
                p[q] = fmaf(hv.z, w2, p[q]);
                p[q] = fmaf(hv.w, w3, p[q]);
            }
        }
        sp2[g][col] = p[0] + p[1] + p[2];
    }
    __syncthreads();
    if (tid < DD)
        outt[row * DD + tid] = (sp2[0][tid] + sp2[1][tid]) * (1.0f / 6.0f);
}

// ---------------------------------------------------------------------------
// Fused gate/mix/LN1 + FFN/LN2. 192 threads / block.
// ---------------------------------------------------------------------------
__global__ __launch_bounds__(FOUR_D) void mixffn_kernel(float* __restrict__ x,
                              const float* __restrict__ p,
                              const float* __restrict__ t,
                              const float* __restrict__ Gw,
                              const float* __restrict__ Gb,
                              const float* __restrict__ n1g,
                              const float* __restrict__ n1b,
                              const float* __restrict__ W1,
                              const float* __restrict__ B1,
                              const float* __restrict__ W2,
                              const float* __restrict__ B2,
                              const float* __restrict__ n2g,
                              const float* __restrict__ n2b) {
    __shared__ float sp[DD], st[DD], sx[DD], sy[DD], sg[2 * DD], sh2[FOUR_D];
    int row = blockIdx.x;
    int tid = threadIdx.x;
    if (tid < DD) {
        sp[tid] = p[row * DD + tid];
        st[tid] = t[row * DD + tid];
        sx[tid] = x[row * DD + tid];
    }
    __syncthreads();
    if (tid < 2 * DD) {
        int d = tid % DD;
        int part = tid / DD;
        const float* src = part ? st : sp;
        const float* gw = Gw + part * DD * DD;
        float s = 0.0f;
        #pragma unroll 8
        for (int c = 0; c < DD; c++) s = fmaf(src[c], gw[c * DD + d], s);
        sg[tid] = s;
    }
    __syncthreads();
    if (tid < DD) {
        float gsum = sg[tid] + sg[DD + tid] + Gb[tid];
        float g = 1.0f / (1.0f + __expf(-gsum));
        sy[tid] = sx[tid] + g * sp[tid] + (1.0f - g) * st[tid];
    }
    __syncthreads();
    if (tid < DD) {
        float mu = 0.0f;
        #pragma unroll 8
        for (int c = 0; c < DD; c++) mu += sy[c];
        mu *= (1.0f / DD);
        float var = 0.0f;
        #pragma unroll 8
        for (int c = 0; c < DD; c++) { float d = sy[c] - mu; var = fmaf(d, d, var); }
        var *= (1.0f / DD);
        sp[tid] = (sy[tid] - mu) * rsqrtf(var + 1e-5f) * n1g[tid] + n1b[tid];
    }
    __syncthreads();
    {
        float h = B1[tid];
        #pragma unroll 8
        for (int c = 0; c < DD; c++) h = fmaf(sp[c], W1[c * FOUR_D + tid], h);
        sh2[tid] = gelu_exact(h);
    }
    __syncthreads();
    if (tid < DD) {
        float o = B2[tid];
        #pragma unroll 8
        for (int k = 0; k < FOUR_D; k++) o = fmaf(sh2[k], W2[k * DD + tid], o);
        sy[tid] = sp[tid] + o;
    }
    __syncthreads();
    if (tid < DD) {
        float mu = 0.0f;
        #pragma unroll 8
        for (int c = 0; c < DD; c++) mu += sy[c];
        mu *= (1.0f / DD);
        float var = 0.0f;
        #pragma unroll 8
        for (int c = 0; c < DD; c++) { float d = sy[c] - mu; var = fmaf(d, d, var); }
        var *= (1.0f / DD);
        x[row * DD + tid] = (sy[tid] - mu) * rsqrtf(var + 1e-5f) * n2g[tid] + n2b[tid];
    }
}

// ---------------------------------------------------------------------------
// Head
// ---------------------------------------------------------------------------
__global__ void head_kernel(const float* __restrict__ x,
                            const float* __restrict__ Hw,
                            const float* __restrict__ Hb,
                            float* __restrict__ out) {
    __shared__ float sx[DD];
    int row = blockIdx.x;
    int tid = threadIdx.x;
    sx[tid] = x[row * DD + tid];
    if (tid < 16) sx[tid + 32] = x[row * DD + tid + 32];
    __syncwarp();
    if (tid < VV) {
        float o = Hb[tid];
        #pragma unroll 8
        for (int d = 0; d < DD; d++) o = fmaf(sx[d], Hw[d * VV + tid], o);
        out[row * VV + tid] = o;
    }
}

// ---------------------------------------------------------------------------
// Launch: triple runs on a second non-blocking stream, overlapped with
// ab+pair on the default stream. Fork/join via events (capture-safe).
// Stream/events are created once (function-local statics) — host objects,
// no device allocation.
// ---------------------------------------------------------------------------
static cudaStream_t side_stream() {
    static cudaStream_t s = [] {
        cudaStream_t t;
        cudaStreamCreateWithFlags(&t, cudaStreamNonBlocking);
        return t;
    }();
    return s;
}
static cudaEvent_t ev_x() {
    static cudaEvent_t e = [] {
        cudaEvent_t t;
        cudaEventCreateWithFlags(&t, cudaEventDisableTiming);
        return t;
    }();
    return e;
}
static cudaEvent_t ev_t() {
    static cudaEvent_t e = [] {
        cudaEvent_t t;
        cudaEventCreateWithFlags(&t, cudaEventDisableTiming);
        return t;
    }();
    return e;
}

extern "C" void kernel_launch(void* const* d_in, const int* in_sizes, int n_in,
                              void* d_out, int out_size) {
    const int*   ids     = (const int*)d_in[0];
    const int*   ji      = (const int*)d_in[1];
    const int*   ki      = (const int*)d_in[2];
    const float* embed   = (const float*)d_in[3];
    const float* pos     = (const float*)d_in[4];
    const float* pair_w1 = (const float*)d_in[5];
    const float* pair_b1 = (const float*)d_in[6];
    const float* pair_w2 = (const float*)d_in[7];
    const float* pair_b2 = (const float*)d_in[8];
    const float* tri_w1  = (const float*)d_in[9];
    const float* tri_b1  = (const float*)d_in[10];
    const float* tri_w2  = (const float*)d_in[11];
    const float* tri_b2  = (const float*)d_in[12];
    const float* gate_w  = (const float*)d_in[13];
    const float* gate_b  = (const float*)d_in[14];
    const float* n1_g    = (const float*)d_in[15];
    const float* n1_b    = (const float*)d_in[16];
    const float* ffn_w1  = (const float*)d_in[17];
    const float* ffn_b1  = (const float*)d_in[18];
    const float* ffn_w2  = (const float*)d_in[19];
    const float* ffn_b2  = (const float*)d_in[20];
    const float* n2_g    = (const float*)d_in[21];
    const float* n2_b    = (const float*)d_in[22];
    const float* head_w  = (const float*)d_in[23];
    const float* head_b  = (const float*)d_in[24];
    float* out = (float*)d_out;

    float* x;  cudaGetSymbolAddress((void**)&x,  g_x);
    float* p;  cudaGetSymbolAddress((void**)&p,  g_p);
    float* t;  cudaGetSymbolAddress((void**)&t,  g_t);
    float* Aa; cudaGetSymbolAddress((void**)&Aa, g_A);
    float* Bb; cudaGetSymbolAddress((void**)&Bb, g_B);

    cudaStream_t s1 = side_stream();
    cudaEvent_t ex = ev_x();
    cudaEvent_t et = ev_t();

    embed_kernel<<<ROWS, DD>>>(ids, embed, pos, x);

    for (int l = 0; l < LL; l++) {
        // Fork: triple on s1 (needs x, ready on stream 0)
        cudaEventRecord(ex, 0);
        cudaStreamWaitEvent(s1, ex, 0);
        triple_kernel<<<ROWS, TWO_D, 0, s1>>>(
            x, ji + l * ROWS * SS, ki + l * ROWS * SS,
            tri_w1 + l * THREE_D * TWO_D, tri_b1 + l * TWO_D,
            tri_w2 + l * TWO_D * DD,      tri_b2 + l * DD, t);
        cudaEventRecord(et, s1);

        // Meanwhile on stream 0: ab + pair
        ab_kernel<<<ROWS / 8, 192>>>(x, pair_w1 + l * TWO_D * TWO_D,
                                     pair_b1 + l * TWO_D, Aa, Bb);
        pair_kernel<<<ROWS, PTHREADS>>>(Aa, Bb,
            pair_w2 + l * TWO_D * DD, pair_b2 + l * DD, p);

        // Join: mixffn needs pair (stream 0 order) and triple (event)
        cudaStreamWaitEvent(0, et, 0);
        mixffn_kernel<<<ROWS, FOUR_D>>>(
            x, p, t,
            gate_w + l * TWO_D * DD, gate_b + l * DD,
            n1_g + l * DD, n1_b + l * DD,
            ffn_w1 + l * DD * FOUR_D, ffn_b1 + l * FOUR_D,
            ffn_w2 + l * FOUR_D * DD, ffn_b2 + l * DD,
            n2_g + l * DD, n2_b + l * DD);
    }

    head_kernel<<<ROWS, 32>>>(x, head_w, head_b, out);
}

// round 16
// speedup vs baseline: 1.0670x; 1.0670x over previous
#include <cuda_runtime.h>
#include <cuda_bf16.h>
#include <math.h>

#define BB 8
#define NN 256
#define DD 48
#define VV 20
#define LL 2
#define SS 6
#define TWO_D 96
#define THREE_D 144
#define FOUR_D 192
#define ROWS (BB*NN)   // 2048

// Scratch
__device__ float g_x[ROWS * DD];
__device__ float g_p[ROWS * DD];
__device__ float g_t[ROWS * DD];
__device__ float g_A[ROWS * TWO_D];   // xi @ W1_top + b1
__device__ float g_B[ROWS * TWO_D];   // xj @ W1_bot

// Fast erf-based gelu (A&S 7.1.26, max abs err 1.5e-7), copysign-free:
// gelu = relu(v) - 0.5|v|*poly*e^{-z^2}
__device__ __forceinline__ float gelu_exact(float v) {
    float az = fabsf(v) * 0.70710678118654752440f;
    float w = fmaf(0.3275911f, az, 1.0f);
    float t;
    asm("rcp.approx.f32 %0, %1;" : "=f"(t) : "f"(w));
    float poly = fmaf(1.061405429f, t, -1.453152027f);
    poly = fmaf(poly, t, 1.421413741f);
    poly = fmaf(poly, t, -0.284496736f);
    poly = fmaf(poly, t, 0.254829592f);
    poly = poly * t;
    float e = __expf(-az * az);
    float s = 0.5f * fabsf(v);
    return fmaf(-s * poly, e, fmaxf(v, 0.0f));
}

__device__ __forceinline__ unsigned smem_u32(const void* p) {
    return (unsigned)__cvta_generic_to_shared(p);
}

__device__ __forceinline__ void ldsm4(unsigned r[4], unsigned addr) {
    asm volatile("ldmatrix.sync.aligned.m8n8.x4.shared.b16 {%0,%1,%2,%3}, [%4];"
                 : "=r"(r[0]), "=r"(r[1]), "=r"(r[2]), "=r"(r[3]) : "r"(addr));
}

__device__ __forceinline__ void mma16816(float c[4], const unsigned a[4],
                                         unsigned b0, unsigned b1) {
    asm volatile("mma.sync.aligned.m16n8k16.row.col.f32.bf16.bf16.f32 "
                 "{%0,%1,%2,%3}, {%4,%5,%6,%7}, {%8,%9}, {%0,%1,%2,%3};"
                 : "+f"(c[0]), "+f"(c[1]), "+f"(c[2]), "+f"(c[3])
                 : "r"(a[0]), "r"(a[1]), "r"(a[2]), "r"(a[3]), "r"(b0), "r"(b1));
}

// ---------------------------------------------------------------------------
// Embed
// ---------------------------------------------------------------------------
__global__ void embed_kernel(const int* __restrict__ ids,
                             const float* __restrict__ embed,
                             const float* __restrict__ pos,
                             float* __restrict__ x) {
    int row = blockIdx.x;
    int n = row & (NN - 1);
    int d = threadIdx.x;
    int id = ids[row];
    x[row * DD + d] = embed[id * DD + d] + pos[n * DD + d];
}

// ---------------------------------------------------------------------------
// Precompute A[row][96] = b1 + xi @ W1[0:48,:],  B[row][96] = xj @ W1[48:96,:]
// ---------------------------------------------------------------------------
__global__ __launch_bounds__(192) void ab_kernel(const float* __restrict__ x,
                          const float* __restrict__ W1,
                          const float* __restrict__ b1,
                          float* __restrict__ A,
                          float* __restrict__ Bv) {
    __shared__ float sx[8][DD];
    int r0 = blockIdx.x * 8;
    int tid = threadIdx.x;
    for (int idx = tid; idx < 8 * DD; idx += 192)
        sx[idx / DD][idx % DD] = x[(r0 + idx / DD) * DD + (idx % DD)];
    __syncthreads();
    int col = tid % TWO_D;
    int part = tid / TWO_D;   // 0 = A, 1 = B
    const float* w = W1 + (part ? DD * TWO_D : 0) + col;
    float acc[8];
    float init = part ? 0.0f : b1[col];
    #pragma unroll
    for (int r = 0; r < 8; r++) acc[r] = init;
    #pragma unroll 4
    for (int k = 0; k < DD; k++) {
        float wv = w[k * TWO_D];
        #pragma unroll
        for (int r = 0; r < 8; r++) acc[r] = fmaf(sx[r][k], wv, acc[r]);
    }
    float* dst = part ? Bv : A;
    #pragma unroll
    for (int r = 0; r < 8; r++) dst[(r0 + r) * TWO_D + col] = acc[r];
}

// ---------------------------------------------------------------------------
// Pair module on tensor cores, k-split H tiles, div-free H-build.
// __launch_bounds__(128,4): leave ~16K regs/SM free so triple_kernel blocks
// (on the side stream) co-schedule with pair. Longest-first row order.
// ---------------------------------------------------------------------------
#define PJT 64
#define PTHREADS 128
#define HPITU 28   // H row pitch in u32 (= 112 B)
#define WPIT 104   // W row pitch in bf16 (= 208 B)

__global__ __launch_bounds__(PTHREADS, 4) void pair_kernel(
    const float* __restrict__ A, const float* __restrict__ Bv,
    const float* __restrict__ W2, const float* __restrict__ B2,
    float* __restrict__ outp) {
    __shared__ __align__(16) unsigned Hhi[PJT * HPITU];
    __shared__ __align__(16) unsigned Hlo[PJT * HPITU];
    __shared__ __align__(16) __nv_bfloat16 Whi[DD * WPIT];
    __shared__ __align__(16) __nv_bfloat16 Wlo[DD * WPIT];
    __shared__ __align__(16) float sA[TWO_D];
    __shared__ float sb2[DD];
    __shared__ float sacc[4 * DD];
    __shared__ float slsum[4];

    // Longest-first: i descends with launch order for better makespan.
    int bid = blockIdx.x;
    int b = bid & 7;
    int i = 255 - (bid >> 3);
    int row = b * NN + i;
    int tid = threadIdx.x;
    int lane = tid & 31;
    int w = tid >> 5;

    // W^T hi/lo build: incremental (k, n4) walk, no per-iter div/mod.
    {
        int k = tid / 12;
        int n4g = tid - k * 12;
        #pragma unroll
        for (int it = 0; it < 9; it++) {
            int n4 = n4g * 4;
            float4 wv = *(const float4*)(W2 + k * DD + n4);
            float vals[4] = {wv.x, wv.y, wv.z, wv.w};
            #pragma unroll
            for (int q = 0; q < 4; q++) {
                int n = n4 + q;
                __nv_bfloat16 hb = __float2bfloat16(vals[q]);
                Whi[n * WPIT + k] = hb;
                Wlo[n * WPIT + k] = __float2bfloat16(vals[q] - __bfloat162float(hb));
            }
            k += 10; n4g += 8;
            if (n4g >= 12) { n4g -= 12; k += 1; }
        }
    }
    if (tid < TWO_D) sA[tid] = A[row * TWO_D + tid];
    if (tid < DD) sb2[tid] = B2[tid];
    __syncthreads();

    float bcol[6][2];
    #pragma unroll
    for (int n = 0; n < 6; n++) {
        bcol[n][0] = sb2[n * 8 + 2 * (lane & 3)];
        bcol[n][1] = sb2[n * 8 + 2 * (lane & 3) + 1];
    }
    unsigned aoff = (unsigned)((w * 16 + (lane & 15)) * 112 + (lane >> 4) * 16);
    unsigned baseAhi = smem_u32(Hhi) + aoff;
    unsigned baseAlo = smem_u32(Hlo) + aoff;
    unsigned boff = (unsigned)((((lane >> 4) << 3) + (lane & 7)) * 208 +
                               ((lane >> 3) & 1) * 16);
    unsigned baseBhi = smem_u32(Whi) + boff;
    unsigned baseBlo = smem_u32(Wlo) + boff;

    int jh = tid >> 1;
    int hs6 = (tid & 1) * 6;
    unsigned* Hhirow = Hhi + jh * HPITU;
    unsigned* Hlorow = Hlo + jh * HPITU;

    float accD[6][2];
    #pragma unroll
    for (int n = 0; n < 6; n++) { accD[n][0] = 0.0f; accD[n][1] = 0.0f; }
    float lsum = 0.0f;

    int numJ = i + 1;
    const float* Bbase = Bv + (b * NN) * TWO_D;

    for (int jbase = 0; jbase < numJ; jbase += PJT) {
        float c[6][4];
        #pragma unroll
        for (int n = 0; n < 6; n++)
            #pragma unroll
            for (int q = 0; q < 4; q++) c[n][q] = 0.0f;

        int jr = jbase + jh; if (jr > i) jr = i;
        const float* brow = Bbase + jr * TWO_D;

        #pragma unroll
        for (int kh = 0; kh < 2; kh++) {
            #pragma unroll
            for (int it = 0; it < 6; it++) {
                int c4 = hs6 + it;
                int kk = kh * 48 + c4 * 4;
                float4 bv = *(const float4*)(brow + kk);
                float4 av = *(const float4*)(sA + kk);
                float h0 = gelu_exact(av.x + bv.x);
                float h1 = gelu_exact(av.y + bv.y);
                float h2 = gelu_exact(av.z + bv.z);
                float h3 = gelu_exact(av.w + bv.w);
                __nv_bfloat162 p01 = __floats2bfloat162_rn(h0, h1);
                __nv_bfloat162 p23 = __floats2bfloat162_rn(h2, h3);
                float r0 = __low2float(p01), r1 = __high2float(p01);
                float r2 = __low2float(p23), r3 = __high2float(p23);
                __nv_bfloat162 q01 = __floats2bfloat162_rn(h0 - r0, h1 - r1);
                __nv_bfloat162 q23 = __floats2bfloat162_rn(h2 - r2, h3 - r3);
                *(uint2*)(Hhirow + c4 * 2) =
                    make_uint2(*(unsigned*)&p01, *(unsigned*)&p23);
                *(uint2*)(Hlorow + c4 * 2) =
                    make_uint2(*(unsigned*)&q01, *(unsigned*)&q23);
            }
            __syncthreads();

            unsigned ahi[4], alo[4], bh[4], bl[4];
            #pragma unroll
            for (int ks = 0; ks < 3; ks++) {
                ldsm4(ahi, baseAhi + ks * 32);
                ldsm4(alo, baseAlo + ks * 32);
                unsigned wko = (unsigned)(kh * 96 + ks * 32);
                #pragma unroll
                for (int np = 0; np < 3; np++) {
                    ldsm4(bh, baseBhi + np * 3328 + wko);
                    ldsm4(bl, baseBlo + np * 3328 + wko);
                    mma16816(c[2 * np + 0], ahi, bh[0], bh[1]);
                    mma16816(c[2 * np + 0], ahi, bl[0], bl[1]);
                    mma16816(c[2 * np + 0], alo, bh[0], bh[1]);
                    mma16816(c[2 * np + 1], ahi, bh[2], bh[3]);
                    mma16816(c[2 * np + 1], ahi, bl[2], bl[3]);
                    mma16816(c[2 * np + 1], alo, bh[2], bh[3]);
                }
            }
            __syncthreads();
        }

        float pv[6][4];
        float sq0 = 0.0f, sq1 = 0.0f;
        #pragma unroll
        for (int n = 0; n < 6; n++) {
            pv[n][0] = c[n][0] + bcol[n][0];
            pv[n][1] = c[n][1] + bcol[n][1];
            pv[n][2] = c[n][2] + bcol[n][0];
            pv[n][3] = c[n][3] + bcol[n][1];
            sq0 = fmaf(pv[n][0], pv[n][0], sq0);
            sq0 = fmaf(pv[n][1], pv[n][1], sq0);
            sq1 = fmaf(pv[n][2], pv[n][2], sq1);
            sq1 = fmaf(pv[n][3], pv[n][3], sq1);
        }
        sq0 += __shfl_xor_sync(0xFFFFFFFFu, sq0, 1);
        sq0 += __shfl_xor_sync(0xFFFFFFFFu, sq0, 2);
        sq1 += __shfl_xor_sync(0xFFFFFFFFu, sq1, 1);
        sq1 += __shfl_xor_sync(0xFFFFFFFFu, sq1, 2);
        int j0 = jbase + w * 16 + (lane >> 2);
        int j1 = j0 + 8;
        float e0 = (j0 <= i) ? __expf(sqrtf(sq0)) : 0.0f;
        float e1 = (j1 <= i) ? __expf(sqrtf(sq1)) : 0.0f;
        #pragma unroll
        for (int n = 0; n < 6; n++) {
            accD[n][0] = fmaf(e0, pv[n][0], fmaf(e1, pv[n][2], accD[n][0]));
            accD[n][1] = fmaf(e0, pv[n][1], fmaf(e1, pv[n][3], accD[n][1]));
        }
        lsum += e0 + e1;
    }

    #pragma unroll
    for (int n = 0; n < 6; n++) {
        #pragma unroll
        for (int q = 0; q < 2; q++) {
            accD[n][q] += __shfl_xor_sync(0xFFFFFFFFu, accD[n][q], 4);
            accD[n][q] += __shfl_xor_sync(0xFFFFFFFFu, accD[n][q], 8);
            accD[n][q] += __shfl_xor_sync(0xFFFFFFFFu, accD[n][q], 16);
        }
    }
    lsum += __shfl_xor_sync(0xFFFFFFFFu, lsum, 4);
    lsum += __shfl_xor_sync(0xFFFFFFFFu, lsum, 8);
    lsum += __shfl_xor_sync(0xFFFFFFFFu, lsum, 16);
    if (lane < 4) {
        #pragma unroll
        for (int n = 0; n < 6; n++) {
            sacc[w * DD + n * 8 + 2 * lane + 0] = accD[n][0];
            sacc[w * DD + n * 8 + 2 * lane + 1] = accD[n][1];
        }
        if (lane == 0) slsum[w] = lsum;
    }
    __syncthreads();

    if (tid < DD) {
        float a = sacc[tid] + sacc[DD + tid] + sacc[2 * DD + tid] + sacc[3 * DD + tid];
        float L = slsum[0] + slsum[1] + slsum[2] + slsum[3];
        outp[row * DD + tid] = a / L;
    }
}

// ---------------------------------------------------------------------------
// Triple module: one row per block, 6-item batch, coalesced W.
// ---------------------------------------------------------------------------
__global__ __launch_bounds__(TWO_D) void triple_kernel(const float* __restrict__ x,
                              const int* __restrict__ ji,
                              const int* __restrict__ ki,
                              const float* __restrict__ W1,
                              const float* __restrict__ B1,
                              const float* __restrict__ W2,
                              const float* __restrict__ B2,
                              float* __restrict__ outt) {
    __shared__ __align__(16) float v[SS][THREE_D];
    __shared__ __align__(16) float hh[SS][TWO_D];
    __shared__ float sp2[2][DD];
    __shared__ int sidx[SS][2];
    int row = blockIdx.x;
    int b = row >> 8;
    int tid = threadIdx.x;     // 96

    if (tid < SS * 2) {
        int s = tid >> 1;
        sidx[s][tid & 1] = (tid & 1) ? ki[row * SS + s] : ji[row * SS + s];
    }
    __syncthreads();

    for (int q = tid; q < SS * 36; q += TWO_D) {
        int s = q / 36;
        int rem = q % 36;
        int seg = rem / 12;
        int f4 = rem % 12;
        int srcrow = (seg == 0) ? row : (b * NN + sidx[s][seg - 1]);
        float4 val = *(const float4*)(x + srcrow * DD + f4 * 4);
        *(float4*)(&v[s][seg * DD + f4 * 4]) = val;
    }
    __syncthreads();

    {
        float h[SS];
        float bb = B1[tid];
        #pragma unroll
        for (int s = 0; s < SS; s++) h[s] = bb;
        const float* w1c = W1 + tid;
        #pragma unroll 3
        for (int k = 0; k < THREE_D; k += 4) {
            float w0 = w1c[(k + 0) * TWO_D];
            float w1 = w1c[(k + 1) * TWO_D];
            float w2 = w1c[(k + 2) * TWO_D];
            float w3 = w1c[(k + 3) * TWO_D];
            #pragma unroll
            for (int s = 0; s < SS; s++) {
                float4 vv = *(const float4*)(&v[s][k]);
                h[s] = fmaf(vv.x, w0, h[s]);
                h[s] = fmaf(vv.y, w1, h[s]);
                h[s] = fmaf(vv.z, w2, h[s]);
                h[s] = fmaf(vv.w, w3, h[s]);
            }
        }
        #pragma unroll
        for (int s = 0; s < SS; s++) hh[s][tid] = gelu_exact(h[s]);
    }
    __syncthreads();

    {
        int col = tid % DD;
        int g = tid / DD;
        float p[3];
        float bb = B2[col];
        #pragma unroll
        for (int q = 0; q < 3; q++) p[q] = bb;
        const float* w2c = W2 + col;
        #pragma unroll 3
        for (int k = 0; k < TWO_D; k += 4) {
            float w0 = w2c[(k + 0) * DD];
            float w1 = w2c[(k + 1) * DD];
            float w2 = w2c[(k + 2) * DD];
            float w3 = w2c[(k + 3) * DD];
            #pragma unroll
            for (int q = 0; q < 3; q++) {
                float4 hv = *(const float4*)(&hh[g * 3 + q][k]);
                p[q] = fmaf(hv.x, w0, p[q]);
                p[q] = fmaf(hv.y, w1, p[q]);
                p[q] = fmaf(hv.z, w2, p[q]);
                p[q] = fmaf(hv.w, w3, p[q]);
            }
        }
        sp2[g][col] = p[0] + p[1] + p[2];
    }
    __syncthreads();
    if (tid < DD)
        outt[row * DD + tid] = (sp2[0][tid] + sp2[1][tid]) * (1.0f / 6.0f);
}

// ---------------------------------------------------------------------------
// Fused gate/mix/LN1 + FFN/LN2. 192 threads / block.
// ---------------------------------------------------------------------------
__global__ __launch_bounds__(FOUR_D) void mixffn_kernel(float* __restrict__ x,
                              const float* __restrict__ p,
                              const float* __restrict__ t,
                              const float* __restrict__ Gw,
                              const float* __restrict__ Gb,
                              const float* __restrict__ n1g,
                              const float* __restrict__ n1b,
                              const float* __restrict__ W1,
                              const float* __restrict__ B1,
                              const float* __restrict__ W2,
                              const float* __restrict__ B2,
                              const float* __restrict__ n2g,
                              const float* __restrict__ n2b) {
    __shared__ float sp[DD], st[DD], sx[DD], sy[DD], sg[2 * DD], sh2[FOUR_D];
    int row = blockIdx.x;
    int tid = threadIdx.x;
    if (tid < DD) {
        sp[tid] = p[row * DD + tid];
        st[tid] = t[row * DD + tid];
        sx[tid] = x[row * DD + tid];
    }
    __syncthreads();
    if (tid < 2 * DD) {
        int d = tid % DD;
        int part = tid / DD;
        const float* src = part ? st : sp;
        const float* gw = Gw + part * DD * DD;
        float s = 0.0f;
        #pragma unroll 8
        for (int c = 0; c < DD; c++) s = fmaf(src[c], gw[c * DD + d], s);
        sg[tid] = s;
    }
    __syncthreads();
    if (tid < DD) {
        float gsum = sg[tid] + sg[DD + tid] + Gb[tid];
        float g = 1.0f / (1.0f + __expf(-gsum));
        sy[tid] = sx[tid] + g * sp[tid] + (1.0f - g) * st[tid];
    }
    __syncthreads();
    if (tid < DD) {
        float mu = 0.0f;
        #pragma unroll 8
        for (int c = 0; c < DD; c++) mu += sy[c];
        mu *= (1.0f / DD);
        float var = 0.0f;
        #pragma unroll 8
        for (int c = 0; c < DD; c++) { float d = sy[c] - mu; var = fmaf(d, d, var); }
        var *= (1.0f / DD);
        sp[tid] = (sy[tid] - mu) * rsqrtf(var + 1e-5f) * n1g[tid] + n1b[tid];
    }
    __syncthreads();
    {
        float h = B1[tid];
        #pragma unroll 8
        for (int c = 0; c < DD; c++) h = fmaf(sp[c], W1[c * FOUR_D + tid], h);
        sh2[tid] = gelu_exact(h);
    }
    __syncthreads();
    if (tid < DD) {
        float o = B2[tid];
        #pragma unroll 8
        for (int k = 0; k < FOUR_D; k++) o = fmaf(sh2[k], W2[k * DD + tid], o);
        sy[tid] = sp[tid] + o;
    }
    __syncthreads();
    if (tid < DD) {
        float mu = 0.0f;
        #pragma unroll 8
        for (int c = 0; c < DD; c++) mu += sy[c];
        mu *= (1.0f / DD);
        float var = 0.0f;
        #pragma unroll 8
        for (int c = 0; c < DD; c++) { float d = sy[c] - mu; var = fmaf(d, d, var); }
        var *= (1.0f / DD);
        x[row * DD + tid] = (sy[tid] - mu) * rsqrtf(var + 1e-5f) * n2g[tid] + n2b[tid];
    }
}

// ---------------------------------------------------------------------------
// Head
// ---------------------------------------------------------------------------
__global__ void head_kernel(const float* __restrict__ x,
                            const float* __restrict__ Hw,
                            const float* __restrict__ Hb,
                            float* __restrict__ out) {
    __shared__ float sx[DD];
    int row = blockIdx.x;
    int tid = threadIdx.x;
    sx[tid] = x[row * DD + tid];
    if (tid < 16) sx[tid + 32] = x[row * DD + tid + 32];
    __syncwarp();
    if (tid < VV) {
        float o = Hb[tid];
        #pragma unroll 8
        for (int d = 0; d < DD; d++) o = fmaf(sx[d], Hw[d * VV + tid], o);
        out[row * VV + tid] = o;
    }
}

// ---------------------------------------------------------------------------
// Launch: triple on side stream overlapped with ab+pair (fork/join events).
// ---------------------------------------------------------------------------
static cudaStream_t side_stream() {
    static cudaStream_t s = [] {
        cudaStream_t t;
        cudaStreamCreateWithFlags(&t, cudaStreamNonBlocking);
        return t;
    }();
    return s;
}
static cudaEvent_t ev_x() {
    static cudaEvent_t e = [] {
        cudaEvent_t t;
        cudaEventCreateWithFlags(&t, cudaEventDisableTiming);
        return t;
    }();
    return e;
}
static cudaEvent_t ev_t() {
    static cudaEvent_t e = [] {
        cudaEvent_t t;
        cudaEventCreateWithFlags(&t, cudaEventDisableTiming);
        return t;
    }();
    return e;
}

extern "C" void kernel_launch(void* const* d_in, const int* in_sizes, int n_in,
                              void* d_out, int out_size) {
    const int*   ids     = (const int*)d_in[0];
    const int*   ji      = (const int*)d_in[1];
    const int*   ki      = (const int*)d_in[2];
    const float* embed   = (const float*)d_in[3];
    const float* pos     = (const float*)d_in[4];
    const float* pair_w1 = (const float*)d_in[5];
    const float* pair_b1 = (const float*)d_in[6];
    const float* pair_w2 = (const float*)d_in[7];
    const float* pair_b2 = (const float*)d_in[8];
    const float* tri_w1  = (const float*)d_in[9];
    const float* tri_b1  = (const float*)d_in[10];
    const float* tri_w2  = (const float*)d_in[11];
    const float* tri_b2  = (const float*)d_in[12];
    const float* gate_w  = (const float*)d_in[13];
    const float* gate_b  = (const float*)d_in[14];
    const float* n1_g    = (const float*)d_in[15];
    const float* n1_b    = (const float*)d_in[16];
    const float* ffn_w1  = (const float*)d_in[17];
    const float* ffn_b1  = (const float*)d_in[18];
    const float* ffn_w2  = (const float*)d_in[19];
    const float* ffn_b2  = (const float*)d_in[20];
    const float* n2_g    = (const float*)d_in[21];
    const float* n2_b    = (const float*)d_in[22];
    const float* head_w  = (const float*)d_in[23];
    const float* head_b  = (const float*)d_in[24];
    float* out = (float*)d_out;

    float* x;  cudaGetSymbolAddress((void**)&x,  g_x);
    float* p;  cudaGetSymbolAddress((void**)&p,  g_p);
    float* t;  cudaGetSymbolAddress((void**)&t,  g_t);
    float* Aa; cudaGetSymbolAddress((void**)&Aa, g_A);
    float* Bb; cudaGetSymbolAddress((void**)&Bb, g_B);

    cudaStream_t s1 = side_stream();
    cudaEvent_t ex = ev_x();
    cudaEvent_t et = ev_t();

    embed_kernel<<<ROWS, DD>>>(ids, embed, pos, x);

    for (int l = 0; l < LL; l++) {
        // Fork: triple on s1 (needs x, ready on stream 0)
        cudaEventRecord(ex, 0);
        cudaStreamWaitEvent(s1, ex, 0);
        triple_kernel<<<ROWS, TWO_D, 0, s1>>>(
            x, ji + l * ROWS * SS, ki + l * ROWS * SS,
            tri_w1 + l * THREE_D * TWO_D, tri_b1 + l * TWO_D,
            tri_w2 + l * TWO_D * DD,      tri_b2 + l * DD, t);
        cudaEventRecord(et, s1);

        // Meanwhile on stream 0: ab + pair
        ab_kernel<<<ROWS / 8, 192>>>(x, pair_w1 + l * TWO_D * TWO_D,
                                     pair_b1 + l * TWO_D, Aa, Bb);
        pair_kernel<<<ROWS, PTHREADS>>>(Aa, Bb,
            pair_w2 + l * TWO_D * DD, pair_b2 + l * DD, p);

        // Join: mixffn needs pair (stream 0 order) and triple (event)
        cudaStreamWaitEvent(0, et, 0);
        mixffn_kernel<<<ROWS, FOUR_D>>>(
            x, p, t,
            gate_w + l * TWO_D * DD, gate_b + l * DD,
            n1_g + l * DD, n1_b + l * DD,
            ffn_w1 + l * DD * FOUR_D, ffn_b1 + l * FOUR_D,
            ffn_w2 + l * FOUR_D * DD, ffn_b2 + l * DD,
            n2_g + l * DD, n2_b + l * DD);
    }

    head_kernel<<<ROWS, 32>>>(x, head_w, head_b, out);
}